// round 15
// baseline (speedup 1.0000x reference)
#include <cuda_runtime.h>
#include <cuda_bf16.h>
#include <mma.h>
#include <math.h>

using namespace nvcuda;

#define BATCH 1024
#define INPUT_SIZE 512
#define HIDDEN 1024
#define N_QP 64
#define M_QP 128
#define QP_ITER 50
#define N_P 2080          // 64*65/2
#define N_HMAT 8192       // 128*64
#define N_OUT 10464       // 2080 + 64 + 8192 + 128
#define HOFF 2144         // N_P + N_QP

__device__ __align__(16) float g_h1[BATCH * HIDDEN];
__device__ __align__(16) float g_h2[BATCH * HIDDEN];
__device__ __align__(16) float g_out3[BATCH * N_OUT];
__device__ __align__(16) __nv_bfloat16 g_a_hi[BATCH * HIDDEN];
__device__ __align__(16) __nv_bfloat16 g_a_lo[BATCH * HIDDEN];
__device__ __align__(16) __nv_bfloat16 g_b_hi[HIDDEN * N_OUT];
__device__ __align__(16) __nv_bfloat16 g_b_lo[HIDDEN * N_OUT];

// ---------------------------------------------------------------------------
// Tiled fp32 SGEMM with fused bias + ReLU — GEMM1 and GEMM2 only.
// ---------------------------------------------------------------------------
template <bool RELU>
__global__ __launch_bounds__(256)
void sgemm_bias(const float* __restrict__ A, const float* __restrict__ B,
                const float* __restrict__ bias, float* __restrict__ C,
                int M, int N, int K)
{
    __shared__ float As[16 * 65];
    __shared__ float Bs[16 * 64];

    const int tid = threadIdx.x;
    const int tx = tid & 15;
    const int ty = tid >> 4;
    const int m0 = blockIdx.y * 64;
    const int n0 = blockIdx.x * 64;

    const int aRow = tid >> 2;
    const int aC4  = tid & 3;
    const int bRow = tid >> 4;
    const int bC4  = tid & 15;

    float acc[4][4] = {};

    for (int k0 = 0; k0 < K; k0 += 16) {
        float4 av = *(const float4*)&A[(size_t)(m0 + aRow) * K + k0 + aC4 * 4];
        int bn = n0 + bC4 * 4;
        float4 bv = make_float4(0.f, 0.f, 0.f, 0.f);
        if (bn < N) bv = *(const float4*)&B[(size_t)(k0 + bRow) * N + bn];

        __syncthreads();
        As[(aC4 * 4 + 0) * 65 + aRow] = av.x;
        As[(aC4 * 4 + 1) * 65 + aRow] = av.y;
        As[(aC4 * 4 + 2) * 65 + aRow] = av.z;
        As[(aC4 * 4 + 3) * 65 + aRow] = av.w;
        *(float4*)&Bs[bRow * 64 + bC4 * 4] = bv;
        __syncthreads();

        #pragma unroll
        for (int k = 0; k < 16; ++k) {
            float4 bb = *(const float4*)&Bs[k * 64 + tx * 4];
            float a0 = As[k * 65 + ty * 4 + 0];
            float a1 = As[k * 65 + ty * 4 + 1];
            float a2 = As[k * 65 + ty * 4 + 2];
            float a3 = As[k * 65 + ty * 4 + 3];
            acc[0][0] = fmaf(a0, bb.x, acc[0][0]);
            acc[0][1] = fmaf(a0, bb.y, acc[0][1]);
            acc[0][2] = fmaf(a0, bb.z, acc[0][2]);
            acc[0][3] = fmaf(a0, bb.w, acc[0][3]);
            acc[1][0] = fmaf(a1, bb.x, acc[1][0]);
            acc[1][1] = fmaf(a1, bb.y, acc[1][1]);
            acc[1][2] = fmaf(a1, bb.z, acc[1][2]);
            acc[1][3] = fmaf(a1, bb.w, acc[1][3]);
            acc[2][0] = fmaf(a2, bb.x, acc[2][0]);
            acc[2][1] = fmaf(a2, bb.y, acc[2][1]);
            acc[2][2] = fmaf(a2, bb.z, acc[2][2]);
            acc[2][3] = fmaf(a2, bb.w, acc[2][3]);
            acc[3][0] = fmaf(a3, bb.x, acc[3][0]);
            acc[3][1] = fmaf(a3, bb.y, acc[3][1]);
            acc[3][2] = fmaf(a3, bb.z, acc[3][2]);
            acc[3][3] = fmaf(a3, bb.w, acc[3][3]);
        }
    }

    #pragma unroll
    for (int ii = 0; ii < 4; ++ii) {
        int m = m0 + ty * 4 + ii;
        #pragma unroll
        for (int jj = 0; jj < 4; ++jj) {
            int n = n0 + tx * 4 + jj;
            if (n < N) {
                float v = acc[ii][jj] + bias[n];
                if (RELU) v = fmaxf(v, 0.f);
                C[(size_t)m * N + n] = v;
            }
        }
    }
}

// ---------------------------------------------------------------------------
// fp32 -> bf16 hi/lo split (elementwise, vectorized).
// ---------------------------------------------------------------------------
__device__ __forceinline__ void split_bf16(float v, __nv_bfloat16& h, __nv_bfloat16& l)
{
    h = __float2bfloat16(v);
    l = __float2bfloat16(v - __bfloat162float(h));
}

__device__ __forceinline__ unsigned pack2(__nv_bfloat16 a, __nv_bfloat16 b)
{
    __nv_bfloat162 t(a, b);
    return *(unsigned*)&t;
}

__global__ __launch_bounds__(256)
void split_kernel(const float* __restrict__ in,
                  __nv_bfloat16* __restrict__ hi,
                  __nv_bfloat16* __restrict__ lo, int n4)
{
    int i = blockIdx.x * 256 + threadIdx.x;
    if (i >= n4) return;
    float4 v = ((const float4*)in)[i];
    __nv_bfloat16 h0, l0, h1, l1, h2, l2, h3, l3;
    split_bf16(v.x, h0, l0); split_bf16(v.y, h1, l1);
    split_bf16(v.z, h2, l2); split_bf16(v.w, h3, l3);
    ((uint2*)hi)[i] = make_uint2(pack2(h0, h1), pack2(h2, h3));
    ((uint2*)lo)[i] = make_uint2(pack2(l0, l1), pack2(l2, l3));
}

// ---------------------------------------------------------------------------
// GEMM3 tensor cores + cp.async double buffering.
// M=1024, N=10464 (=109*96), K=1024. CTA 128x96, k-step 32, 8 warps.
// ---------------------------------------------------------------------------
#define G3_N   10464
#define G3_K   1024
#define G3_AS  40             // A smem stride (bf16); 80 B, 16B-multiple
#define G3_BS  104            // B smem stride (bf16); 208 B, 16B-multiple
#define G3_SA  (128 * G3_AS)  // 5120 bf16 per A stage
#define G3_SB  (32 * G3_BS)   // 3328 bf16 per B stage
#define G3_SN  100            // epilogue staging stride (floats)
#define G3_SMEM_BYTES ((4 * G3_SA + 4 * G3_SB) * 2)   // 67584 B (> sC 51200)

__device__ __forceinline__ void cp16(void* smem, const void* gmem)
{
    unsigned saddr = (unsigned)__cvta_generic_to_shared(smem);
    asm volatile("cp.async.cg.shared.global [%0], [%1], 16;\n"
                 :: "r"(saddr), "l"(gmem));
}

__device__ __forceinline__ void g3_load_tile(
    int t, int m0, int n0, int k0,
    const __nv_bfloat16* __restrict__ Ah, const __nv_bfloat16* __restrict__ Al,
    const __nv_bfloat16* __restrict__ Bh, const __nv_bfloat16* __restrict__ Bl,
    __nv_bfloat16* sAh, __nv_bfloat16* sAl,
    __nv_bfloat16* sBh, __nv_bfloat16* sBl)
{
    #pragma unroll
    for (int i = 0; i < 2; ++i) {
        int l   = t * 2 + i;          // 0..511
        int row = l >> 2;             // 0..127
        int c8  = (l & 3) * 8;        // 0,8,16,24
        size_t src = (size_t)(m0 + row) * G3_K + k0 + c8;
        cp16(sAh + row * G3_AS + c8, Ah + src);
        cp16(sAl + row * G3_AS + c8, Al + src);
    }
    #pragma unroll
    for (int i = 0; i < 3; ++i) {
        int l   = t + 256 * i;        // 0..767
        int mat = (l >= 384);
        int ll  = l - mat * 384;
        int row = ll / 12;            // 0..31
        int c8  = (ll % 12) * 8;      // 0..88
        const __nv_bfloat16* src = mat ? Bl : Bh;
        __nv_bfloat16*       dst = mat ? sBl : sBh;
        cp16(dst + row * G3_BS + c8, src + (size_t)(k0 + row) * G3_N + n0 + c8);
    }
}

__global__ __launch_bounds__(256, 2)
void gemm3_bf16(const __nv_bfloat16* __restrict__ Ah, const __nv_bfloat16* __restrict__ Al,
                const __nv_bfloat16* __restrict__ Bh, const __nv_bfloat16* __restrict__ Bl,
                const float* __restrict__ bias, float* __restrict__ C)
{
    extern __shared__ __align__(16) unsigned char smraw[];
    __nv_bfloat16* base  = (__nv_bfloat16*)smraw;
    __nv_bfloat16* pAhi  = base;                 // 2 stages of G3_SA
    __nv_bfloat16* pAlo  = base + 2 * G3_SA;
    __nv_bfloat16* pBhi  = base + 4 * G3_SA;     // 2 stages of G3_SB
    __nv_bfloat16* pBlo  = base + 4 * G3_SA + 2 * G3_SB;
    float* sC = (float*)smraw;                   // epilogue reuse

    const int t    = threadIdx.x;
    const int warp = t >> 5;
    const int wm   = warp & 3;
    const int wn   = warp >> 2;
    const int n0   = blockIdx.x * 96;
    const int m0   = blockIdx.y * 128;

    wmma::fragment<wmma::accumulator, 16, 16, 16, float> acc[2][3];
    #pragma unroll
    for (int i = 0; i < 2; ++i)
        #pragma unroll
        for (int j = 0; j < 3; ++j)
            wmma::fill_fragment(acc[i][j], 0.f);

    // Prologue: stage 0 loads in flight
    g3_load_tile(t, m0, n0, 0, Ah, Al, Bh, Bl, pAhi, pAlo, pBhi, pBlo);
    asm volatile("cp.async.commit_group;\n" ::: "memory");

    for (int k0 = 0; k0 < G3_K; k0 += 32) {
        const int cur = (k0 >> 5) & 1;
        asm volatile("cp.async.wait_group 0;\n" ::: "memory");
        __syncthreads();   // data visible to all; all warps done with prev compute

        if (k0 + 32 < G3_K) {
            const int nxt = cur ^ 1;
            g3_load_tile(t, m0, n0, k0 + 32, Ah, Al, Bh, Bl,
                         pAhi + nxt * G3_SA, pAlo + nxt * G3_SA,
                         pBhi + nxt * G3_SB, pBlo + nxt * G3_SB);
            asm volatile("cp.async.commit_group;\n" ::: "memory");
        }

        __nv_bfloat16* sAh = pAhi + cur * G3_SA;
        __nv_bfloat16* sAl = pAlo + cur * G3_SA;
        __nv_bfloat16* sBh = pBhi + cur * G3_SB;
        __nv_bfloat16* sBl = pBlo + cur * G3_SB;

        #pragma unroll
        for (int ks = 0; ks < 32; ks += 16) {
            wmma::fragment<wmma::matrix_a, 16, 16, 16, __nv_bfloat16, wmma::row_major> a_hi[2], a_lo[2];
            wmma::fragment<wmma::matrix_b, 16, 16, 16, __nv_bfloat16, wmma::row_major> b_hi[3], b_lo[3];
            #pragma unroll
            for (int i = 0; i < 2; ++i) {
                wmma::load_matrix_sync(a_hi[i], sAh + (wm * 32 + i * 16) * G3_AS + ks, G3_AS);
                wmma::load_matrix_sync(a_lo[i], sAl + (wm * 32 + i * 16) * G3_AS + ks, G3_AS);
            }
            #pragma unroll
            for (int j = 0; j < 3; ++j) {
                wmma::load_matrix_sync(b_hi[j], sBh + ks * G3_BS + wn * 48 + j * 16, G3_BS);
                wmma::load_matrix_sync(b_lo[j], sBl + ks * G3_BS + wn * 48 + j * 16, G3_BS);
            }
            #pragma unroll
            for (int i = 0; i < 2; ++i)
                #pragma unroll
                for (int j = 0; j < 3; ++j) {
                    wmma::mma_sync(acc[i][j], a_hi[i], b_hi[j], acc[i][j]);
                    wmma::mma_sync(acc[i][j], a_hi[i], b_lo[j], acc[i][j]);
                    wmma::mma_sync(acc[i][j], a_lo[i], b_hi[j], acc[i][j]);
                }
        }
    }

    // Epilogue
    __syncthreads();
    #pragma unroll
    for (int i = 0; i < 2; ++i)
        #pragma unroll
        for (int j = 0; j < 3; ++j)
            wmma::store_matrix_sync(sC + (wm * 32 + i * 16) * G3_SN + wn * 48 + j * 16,
                                    acc[i][j], G3_SN, wmma::mem_row_major);
    __syncthreads();
    for (int l = t; l < 128 * 96; l += 256) {
        int row = l / 96, col = l % 96;
        C[(size_t)(m0 + row) * G3_N + n0 + col] = sC[row * G3_SN + col] + bias[n0 + col];
    }
}

// ---------------------------------------------------------------------------
// QP solver — round-4 structure, but NO rH register copy (rows read from sH,
// stride 68 so row bases are 16B-aligned). Arrays: rM[16] only.
// ---------------------------------------------------------------------------
__device__ __forceinline__ float sel16(const float* r, int kj) {
    float v = r[0];
    #pragma unroll
    for (int j = 1; j < 16; ++j) v = (j == kj) ? r[j] : v;
    return v;
}

#define HS 68   // sH row stride (multiple of 4)
#define SOLVER_SMEM_FLOATS (128 * HS + 64 * 65)

__global__ __launch_bounds__(256, 2)
void solver_kernel(const float* __restrict__ out3, float* __restrict__ xs)
{
    extern __shared__ __align__(16) float smdyn[];
    float* sH = smdyn;              // 128*HS  (H, persistent)
    float* sQ = sH + 128 * HS;      // 64*65   (L, then dead)

    __shared__ __align__(16) float spiv[2 * 64];
    __shared__ __align__(16) float sxbar[64];
    __shared__ __align__(16) float st[64];
    __shared__ __align__(16) float slam[128];
    __shared__ __align__(16) float sb[128];
    __shared__ __align__(16) float sq[64];
    __shared__ __align__(16) float sv[64];
    __shared__ __align__(16) float sw[128];
    __shared__ float spart[8];
    __shared__ float s_scal, s_tau;

    const int t    = threadIdx.x;
    const int lane = t & 31;
    const int warp = t >> 5;
    const int r    = t >> 1;   // 0..127
    const int h    = t & 1;
    const int c    = t >> 2;   // 0..63
    const int g    = t & 3;

    const float* row = out3 + (size_t)blockIdx.x * N_OUT;
    const unsigned FULL = 0xffffffffu;

    // ---- Load H into smem (coalesced gmem float4 -> aligned smem float4) ----
    {
        const float4* src = (const float4*)(row + HOFF + r * 64 + 32 * h);
        float4* dst = (float4*)(sH + r * HS + 32 * h);
        #pragma unroll
        for (int k4 = 0; k4 < 8; ++k4) dst[k4] = src[k4];
    }
    if (t < 64)  sq[t] = row[N_P + t];
    if (t < 128) sb[t] = row[HOFF + N_HMAT + t];
    if (t < 64)  sv[t] = 0.125f;
    __syncthreads();

    // ================= Power iteration =================
    for (int pit = 0; pit < 10; ++pit) {
        {   // w = H v   (r, h)
            const float4* hr = (const float4*)(sH + r * HS + 32 * h);
            const float4* x4 = (const float4*)(sv + 32 * h);
            float a0=0.f,a1=0.f,a2=0.f,a3=0.f;
            #pragma unroll
            for (int k4 = 0; k4 < 8; ++k4) {
                float4 hv = hr[k4];
                float4 xv = x4[k4];
                a0 = fmaf(hv.x, xv.x, a0);
                a1 = fmaf(hv.y, xv.y, a1);
                a2 = fmaf(hv.z, xv.z, a2);
                a3 = fmaf(hv.w, xv.w, a3);
            }
            float s = (a0 + a1) + (a2 + a3);
            s += __shfl_xor_sync(FULL, s, 1);
            if (h == 0) sw[r] = s;
        }
        __syncthreads();
        {   // p = (H^T w)[c]  (c, g)
            float a0=0.f,a1=0.f,a2=0.f,a3=0.f;
            #pragma unroll
            for (int j0 = 0; j0 < 32; j0 += 4) {
                int jj0 = (j0 + 0 + 8 * g) & 31;
                int jj1 = (j0 + 1 + 8 * g) & 31;
                int jj2 = (j0 + 2 + 8 * g) & 31;
                int jj3 = (j0 + 3 + 8 * g) & 31;
                a0 = fmaf(sH[(32*g + jj0) * HS + c], sw[32*g + jj0], a0);
                a1 = fmaf(sH[(32*g + jj1) * HS + c], sw[32*g + jj1], a1);
                a2 = fmaf(sH[(32*g + jj2) * HS + c], sw[32*g + jj2], a2);
                a3 = fmaf(sH[(32*g + jj3) * HS + c], sw[32*g + jj3], a3);
            }
            float p = (a0 + a1) + (a2 + a3);
            p += __shfl_xor_sync(FULL, p, 1);
            p += __shfl_xor_sync(FULL, p, 2);
            float pp = (g == 0) ? p * p : 0.f;
            #pragma unroll
            for (int off = 16; off >= 1; off >>= 1)
                pp += __shfl_xor_sync(FULL, pp, off);
            if (lane == 0) spart[warp] = pp;
            __syncthreads();
            if (t == 0) {
                float sm = 0.f;
                #pragma unroll
                for (int i = 0; i < 8; ++i) sm += spart[i];
                s_scal = sqrtf(sm) + 1e-12f;
            }
            __syncthreads();
            if (g == 0) sv[c] = p / s_scal;
        }
        __syncthreads();
    }

    // ---- tau = 0.9/(||H v|| + 1e-6) ----
    {
        const float4* hr = (const float4*)(sH + r * HS + 32 * h);
        const float4* x4 = (const float4*)(sv + 32 * h);
        float a0=0.f,a1=0.f,a2=0.f,a3=0.f;
        #pragma unroll
        for (int k4 = 0; k4 < 8; ++k4) {
            float4 hv = hr[k4];
            float4 xv = x4[k4];
            a0 = fmaf(hv.x, xv.x, a0);
            a1 = fmaf(hv.y, xv.y, a1);
            a2 = fmaf(hv.z, xv.z, a2);
            a3 = fmaf(hv.w, xv.w, a3);
        }
        float s = (a0 + a1) + (a2 + a3);
        s += __shfl_xor_sync(FULL, s, 1);
        float pp = (h == 0) ? s * s : 0.f;
        #pragma unroll
        for (int off = 16; off >= 1; off >>= 1)
            pp += __shfl_xor_sync(FULL, pp, off);
        if (lane == 0) spart[warp] = pp;
        __syncthreads();
        if (t == 0) {
            float sm = 0.f;
            #pragma unroll
            for (int i = 0; i < 8; ++i) sm += spart[i];
            s_tau = 0.9f / (sqrtf(sm) + 1e-6f);
        }
    }

    // ================= Build L =================
    for (int idx = t; idx < 64 * 65; idx += 256) sQ[idx] = 0.f;
    __syncthreads();
    for (int idx = t; idx < N_P; idx += 256) {
        float p = row[idx];
        int rr = (int)((sqrtf(8.f * (float)idx + 1.f) - 1.f) * 0.5f);
        while ((rr * (rr + 1)) / 2 > idx) --rr;
        while (((rr + 1) * (rr + 2)) / 2 <= idx) ++rr;
        int cc = idx - (rr * (rr + 1)) / 2;
        float val;
        if (cc == rr) {
            float sp = fmaxf(p, 0.f) + log1pf(expf(-fabsf(p)));
            val = 0.1f + sp;
        } else {
            val = p;
        }
        sQ[rr * 65 + cc] = val;
    }
    __syncthreads();
    const float tau = s_tau;
    const float sig = tau;

    // ================= rM = I + tau * (L L^T) slice (c, g) ==========
    float rM[16];
    #pragma unroll
    for (int j = 0; j < 16; ++j) rM[j] = 0.f;
    for (int k = 0; k < 64; ++k) {
        float a = sQ[c * 65 + k];
        #pragma unroll
        for (int j = 0; j < 16; ++j)
            rM[j] = fmaf(a, sQ[(16 * g + j) * 65 + k], rM[j]);
    }
    #pragma unroll
    for (int j = 0; j < 16; ++j) {
        int col = 16 * g + j;
        rM[j] = tau * rM[j] + ((col == c) ? 1.f : 0.f);
    }
    __syncthreads();

    // ================= Gauss-Jordan inverse ============
    for (int k = 0; k < 64; ++k) {
        const int kc = k >> 4, kj = k & 15;
        float* buf = spiv + (k & 1) * 64;
        float praw = __shfl_sync(FULL, sel16(rM, kj), (lane & ~3) | kc);
        if (c == k) {
            float pinv = 1.f / praw;
            #pragma unroll
            for (int j = 0; j < 16; ++j) {
                bool isk = (g == kc) && (j == kj);
                rM[j] = isk ? pinv : rM[j] * pinv;
            }
            *(float4*)&buf[16*g +  0] = make_float4(rM[0],  rM[1],  rM[2],  rM[3]);
            *(float4*)&buf[16*g +  4] = make_float4(rM[4],  rM[5],  rM[6],  rM[7]);
            *(float4*)&buf[16*g +  8] = make_float4(rM[8],  rM[9],  rM[10], rM[11]);
            *(float4*)&buf[16*g + 12] = make_float4(rM[12], rM[13], rM[14], rM[15]);
        }
        __syncthreads();
        if (c != k) {
            const float f = praw;
            float4 p0 = *(const float4*)&buf[16*g +  0];
            float4 p1 = *(const float4*)&buf[16*g +  4];
            float4 p2 = *(const float4*)&buf[16*g +  8];
            float4 p3 = *(const float4*)&buf[16*g + 12];
            float pv[16] = {p0.x,p0.y,p0.z,p0.w, p1.x,p1.y,p1.z,p1.w,
                            p2.x,p2.y,p2.z,p2.w, p3.x,p3.y,p3.z,p3.w};
            #pragma unroll
            for (int j = 0; j < 16; ++j) {
                bool isk = (g == kc) && (j == kj);
                float upd = fmaf(-f, pv[j], rM[j]);
                rM[j] = isk ? (-f * pv[j]) : upd;
            }
        }
    }
    __syncthreads();

    // ================= QP iterations =================
    if (t < 64)  { sxbar[t] = 0.f; st[t] = 0.f; }
    if (t < 128) slam[t] = 0.f;
    float xp = 0.f;
    __syncthreads();

    for (int it = 0; it < QP_ITER; ++it) {
        {   // lam = relu(lam - sig*(H xbar + b))  (r, h); rows from sH
            const float4* hr = (const float4*)(sH + r * HS + 32 * h);
            const float4* x4 = (const float4*)(sxbar + 32 * h);
            float a0=0.f,a1=0.f,a2=0.f,a3=0.f;
            #pragma unroll
            for (int k4 = 0; k4 < 8; ++k4) {
                float4 hv = hr[k4];
                float4 xv = x4[k4];
                a0 = fmaf(hv.x, xv.x, a0);
                a1 = fmaf(hv.y, xv.y, a1);
                a2 = fmaf(hv.z, xv.z, a2);
                a3 = fmaf(hv.w, xv.w, a3);
            }
            float s = (a0 + a1) + (a2 + a3);
            s += __shfl_xor_sync(FULL, s, 1);
            if (h == 0) slam[r] = fmaxf(0.f, slam[r] - sig * (s + sb[r]));
        }
        __syncthreads();
        {   // t = xp + tau*(H^T lam - q)   (c, g)
            float a0=0.f,a1=0.f,a2=0.f,a3=0.f;
            #pragma unroll
            for (int j0 = 0; j0 < 32; j0 += 4) {
                int jj0 = (j0 + 0 + 8 * g) & 31;
                int jj1 = (j0 + 1 + 8 * g) & 31;
                int jj2 = (j0 + 2 + 8 * g) & 31;
                int jj3 = (j0 + 3 + 8 * g) & 31;
                a0 = fmaf(sH[(32*g + jj0) * HS + c], slam[32*g + jj0], a0);
                a1 = fmaf(sH[(32*g + jj1) * HS + c], slam[32*g + jj1], a1);
                a2 = fmaf(sH[(32*g + jj2) * HS + c], slam[32*g + jj2], a2);
                a3 = fmaf(sH[(32*g + jj3) * HS + c], slam[32*g + jj3], a3);
            }
            float p = (a0 + a1) + (a2 + a3);
            p += __shfl_xor_sync(FULL, p, 1);
            p += __shfl_xor_sync(FULL, p, 2);
            if (g == 0) st[c] = xp + tau * (p - sq[c]);
        }
        __syncthreads();
        {   // xn = Minv t ; xbar = 2 xn - xp ; xp = xn  (c, g)
            const float4* t4 = (const float4*)(st + 16 * g);
            float4 t0 = t4[0], t1 = t4[1], t2 = t4[2], t3 = t4[3];
            float a0=0.f,a1=0.f,a2=0.f,a3=0.f;
            a0 = fmaf(rM[0],  t0.x, a0); a1 = fmaf(rM[1],  t0.y, a1);
            a2 = fmaf(rM[2],  t0.z, a2); a3 = fmaf(rM[3],  t0.w, a3);
            a0 = fmaf(rM[4],  t1.x, a0); a1 = fmaf(rM[5],  t1.y, a1);
            a2 = fmaf(rM[6],  t1.z, a2); a3 = fmaf(rM[7],  t1.w, a3);
            a0 = fmaf(rM[8],  t2.x, a0); a1 = fmaf(rM[9],  t2.y, a1);
            a2 = fmaf(rM[10], t2.z, a2); a3 = fmaf(rM[11], t2.w, a3);
            a0 = fmaf(rM[12], t3.x, a0); a1 = fmaf(rM[13], t3.y, a1);
            a2 = fmaf(rM[14], t3.z, a2); a3 = fmaf(rM[15], t3.w, a3);
            float p = (a0 + a1) + (a2 + a3);
            p += __shfl_xor_sync(FULL, p, 1);
            p += __shfl_xor_sync(FULL, p, 2);
            if (g == 0) {
                sxbar[c] = 2.f * p - xp;
                xp = p;
            }
        }
        __syncthreads();
    }

    if (g == 0) xs[(size_t)blockIdx.x * N_QP + c] = xp;
}

// ---------------------------------------------------------------------------
// Launch
// ---------------------------------------------------------------------------
extern "C" void kernel_launch(void* const* d_in, const int* in_sizes, int n_in,
                              void* d_out, int out_size)
{
    const float* x  = (const float*)d_in[0];
    const float* W1 = (const float*)d_in[1];
    const float* b1 = (const float*)d_in[2];
    const float* W2 = (const float*)d_in[3];
    const float* b2 = (const float*)d_in[4];
    const float* W3 = (const float*)d_in[5];
    const float* b3 = (const float*)d_in[6];
    float* out = (float*)d_out;

    float *p_h1, *p_h2, *p_out3;
    __nv_bfloat16 *p_ahi, *p_alo, *p_bhi, *p_blo;
    cudaGetSymbolAddress((void**)&p_h1, g_h1);
    cudaGetSymbolAddress((void**)&p_h2, g_h2);
    cudaGetSymbolAddress((void**)&p_out3, g_out3);
    cudaGetSymbolAddress((void**)&p_ahi, g_a_hi);
    cudaGetSymbolAddress((void**)&p_alo, g_a_lo);
    cudaGetSymbolAddress((void**)&p_bhi, g_b_hi);
    cudaGetSymbolAddress((void**)&p_blo, g_b_lo);

    {
        dim3 grid(HIDDEN / 64, BATCH / 64);
        sgemm_bias<true><<<grid, 256>>>(x, W1, b1, p_h1, BATCH, HIDDEN, INPUT_SIZE);
    }
    {
        dim3 grid(HIDDEN / 64, BATCH / 64);
        sgemm_bias<true><<<grid, 256>>>(p_h1, W2, b2, p_h2, BATCH, HIDDEN, HIDDEN);
    }
    {
        int n4 = (HIDDEN * N_OUT) / 4;
        split_kernel<<<(n4 + 255) / 256, 256>>>(W3, p_bhi, p_blo, n4);
    }
    {
        int n4 = (BATCH * HIDDEN) / 4;
        split_kernel<<<(n4 + 255) / 256, 256>>>(p_h2, p_ahi, p_alo, n4);
    }
    {
        cudaFuncSetAttribute(gemm3_bf16,
                             cudaFuncAttributeMaxDynamicSharedMemorySize,
                             G3_SMEM_BYTES);
        dim3 grid(G3_N / 96, BATCH / 128);   // 109 x 8
        gemm3_bf16<<<grid, 256, G3_SMEM_BYTES>>>(p_ahi, p_alo, p_bhi, p_blo, b3, p_out3);
    }
    {
        const size_t smem_bytes = (size_t)SOLVER_SMEM_FLOATS * sizeof(float);
        cudaFuncSetAttribute(solver_kernel,
                             cudaFuncAttributeMaxDynamicSharedMemorySize,
                             (int)smem_bytes);
        solver_kernel<<<BATCH, 256, smem_bytes>>>(p_out3, out);
    }
}

// round 16
// speedup vs baseline: 1.3018x; 1.3018x over previous
#include <cuda_runtime.h>
#include <cuda_bf16.h>
#include <mma.h>
#include <math.h>

using namespace nvcuda;

#define BATCH 1024
#define INPUT_SIZE 512
#define HIDDEN 1024
#define N_QP 64
#define M_QP 128
#define QP_ITER 50
#define N_P 2080          // 64*65/2
#define N_HMAT 8192       // 128*64
#define N_OUT 10464       // 2080 + 64 + 8192 + 128
#define HOFF 2144         // N_P + N_QP

__device__ __align__(16) float g_h1[BATCH * HIDDEN];
__device__ __align__(16) float g_h2[BATCH * HIDDEN];
__device__ __align__(16) float g_out3[BATCH * N_OUT];
__device__ __align__(16) __nv_bfloat16 g_a_hi[BATCH * HIDDEN];
__device__ __align__(16) __nv_bfloat16 g_a_lo[BATCH * HIDDEN];
__device__ __align__(16) __nv_bfloat16 g_b_hi[HIDDEN * N_OUT];
__device__ __align__(16) __nv_bfloat16 g_b_lo[HIDDEN * N_OUT];

// ---------------------------------------------------------------------------
// Tiled fp32 SGEMM with fused bias + ReLU — GEMM1 and GEMM2 only.
// ---------------------------------------------------------------------------
template <bool RELU>
__global__ __launch_bounds__(256)
void sgemm_bias(const float* __restrict__ A, const float* __restrict__ B,
                const float* __restrict__ bias, float* __restrict__ C,
                int M, int N, int K)
{
    __shared__ float As[16 * 65];
    __shared__ float Bs[16 * 64];

    const int tid = threadIdx.x;
    const int tx = tid & 15;
    const int ty = tid >> 4;
    const int m0 = blockIdx.y * 64;
    const int n0 = blockIdx.x * 64;

    const int aRow = tid >> 2;
    const int aC4  = tid & 3;
    const int bRow = tid >> 4;
    const int bC4  = tid & 15;

    float acc[4][4] = {};

    for (int k0 = 0; k0 < K; k0 += 16) {
        float4 av = *(const float4*)&A[(size_t)(m0 + aRow) * K + k0 + aC4 * 4];
        int bn = n0 + bC4 * 4;
        float4 bv = make_float4(0.f, 0.f, 0.f, 0.f);
        if (bn < N) bv = *(const float4*)&B[(size_t)(k0 + bRow) * N + bn];

        __syncthreads();
        As[(aC4 * 4 + 0) * 65 + aRow] = av.x;
        As[(aC4 * 4 + 1) * 65 + aRow] = av.y;
        As[(aC4 * 4 + 2) * 65 + aRow] = av.z;
        As[(aC4 * 4 + 3) * 65 + aRow] = av.w;
        *(float4*)&Bs[bRow * 64 + bC4 * 4] = bv;
        __syncthreads();

        #pragma unroll
        for (int k = 0; k < 16; ++k) {
            float4 bb = *(const float4*)&Bs[k * 64 + tx * 4];
            float a0 = As[k * 65 + ty * 4 + 0];
            float a1 = As[k * 65 + ty * 4 + 1];
            float a2 = As[k * 65 + ty * 4 + 2];
            float a3 = As[k * 65 + ty * 4 + 3];
            acc[0][0] = fmaf(a0, bb.x, acc[0][0]);
            acc[0][1] = fmaf(a0, bb.y, acc[0][1]);
            acc[0][2] = fmaf(a0, bb.z, acc[0][2]);
            acc[0][3] = fmaf(a0, bb.w, acc[0][3]);
            acc[1][0] = fmaf(a1, bb.x, acc[1][0]);
            acc[1][1] = fmaf(a1, bb.y, acc[1][1]);
            acc[1][2] = fmaf(a1, bb.z, acc[1][2]);
            acc[1][3] = fmaf(a1, bb.w, acc[1][3]);
            acc[2][0] = fmaf(a2, bb.x, acc[2][0]);
            acc[2][1] = fmaf(a2, bb.y, acc[2][1]);
            acc[2][2] = fmaf(a2, bb.z, acc[2][2]);
            acc[2][3] = fmaf(a2, bb.w, acc[2][3]);
            acc[3][0] = fmaf(a3, bb.x, acc[3][0]);
            acc[3][1] = fmaf(a3, bb.y, acc[3][1]);
            acc[3][2] = fmaf(a3, bb.z, acc[3][2]);
            acc[3][3] = fmaf(a3, bb.w, acc[3][3]);
        }
    }

    #pragma unroll
    for (int ii = 0; ii < 4; ++ii) {
        int m = m0 + ty * 4 + ii;
        #pragma unroll
        for (int jj = 0; jj < 4; ++jj) {
            int n = n0 + tx * 4 + jj;
            if (n < N) {
                float v = acc[ii][jj] + bias[n];
                if (RELU) v = fmaxf(v, 0.f);
                C[(size_t)m * N + n] = v;
            }
        }
    }
}

// ---------------------------------------------------------------------------
// fp32 -> bf16 hi/lo split (elementwise, vectorized).
// ---------------------------------------------------------------------------
__device__ __forceinline__ void split_bf16(float v, __nv_bfloat16& h, __nv_bfloat16& l)
{
    h = __float2bfloat16(v);
    l = __float2bfloat16(v - __bfloat162float(h));
}

__device__ __forceinline__ unsigned pack2(__nv_bfloat16 a, __nv_bfloat16 b)
{
    __nv_bfloat162 t(a, b);
    return *(unsigned*)&t;
}

__global__ __launch_bounds__(256)
void split_kernel(const float* __restrict__ in,
                  __nv_bfloat16* __restrict__ hi,
                  __nv_bfloat16* __restrict__ lo, int n4)
{
    int i = blockIdx.x * 256 + threadIdx.x;
    if (i >= n4) return;
    float4 v = ((const float4*)in)[i];
    __nv_bfloat16 h0, l0, h1, l1, h2, l2, h3, l3;
    split_bf16(v.x, h0, l0); split_bf16(v.y, h1, l1);
    split_bf16(v.z, h2, l2); split_bf16(v.w, h3, l3);
    ((uint2*)hi)[i] = make_uint2(pack2(h0, h1), pack2(h2, h3));
    ((uint2*)lo)[i] = make_uint2(pack2(l0, l1), pack2(l2, l3));
}

// ---------------------------------------------------------------------------
// GEMM3 tensor cores + cp.async double buffering (ONLY change vs round 14).
// M=1024, N=10464 (=109*96), K=1024. CTA 128x96, k-step 32, 8 warps.
// ---------------------------------------------------------------------------
#define G3_N   10464
#define G3_K   1024
#define G3_AS  40             // A smem stride (bf16); 80 B
#define G3_BS  104            // B smem stride (bf16); 208 B
#define G3_SA  (128 * G3_AS)  // 5120 bf16 per A stage
#define G3_SB  (32 * G3_BS)   // 3328 bf16 per B stage
#define G3_SN  100            // epilogue staging stride (floats)
#define G3_SMEM_BYTES ((4 * G3_SA + 4 * G3_SB) * 2)   // 67584 B (> sC 51200)

__device__ __forceinline__ void cp16(void* smem, const void* gmem)
{
    unsigned saddr = (unsigned)__cvta_generic_to_shared(smem);
    asm volatile("cp.async.cg.shared.global [%0], [%1], 16;\n"
                 :: "r"(saddr), "l"(gmem));
}

__device__ __forceinline__ void g3_load_tile(
    int t, int m0, int n0, int k0,
    const __nv_bfloat16* __restrict__ Ah, const __nv_bfloat16* __restrict__ Al,
    const __nv_bfloat16* __restrict__ Bh, const __nv_bfloat16* __restrict__ Bl,
    __nv_bfloat16* sAh, __nv_bfloat16* sAl,
    __nv_bfloat16* sBh, __nv_bfloat16* sBl)
{
    #pragma unroll
    for (int i = 0; i < 2; ++i) {
        int l   = t * 2 + i;          // 0..511
        int row = l >> 2;             // 0..127
        int c8  = (l & 3) * 8;        // 0,8,16,24
        size_t src = (size_t)(m0 + row) * G3_K + k0 + c8;
        cp16(sAh + row * G3_AS + c8, Ah + src);
        cp16(sAl + row * G3_AS + c8, Al + src);
    }
    #pragma unroll
    for (int i = 0; i < 3; ++i) {
        int l   = t + 256 * i;        // 0..767
        int mat = (l >= 384);
        int ll  = l - mat * 384;
        int row = ll / 12;            // 0..31
        int c8  = (ll % 12) * 8;      // 0..88
        const __nv_bfloat16* src = mat ? Bl : Bh;
        __nv_bfloat16*       dst = mat ? sBl : sBh;
        cp16(dst + row * G3_BS + c8, src + (size_t)(k0 + row) * G3_N + n0 + c8);
    }
}

__global__ __launch_bounds__(256, 2)
void gemm3_bf16(const __nv_bfloat16* __restrict__ Ah, const __nv_bfloat16* __restrict__ Al,
                const __nv_bfloat16* __restrict__ Bh, const __nv_bfloat16* __restrict__ Bl,
                const float* __restrict__ bias, float* __restrict__ C)
{
    extern __shared__ __align__(16) unsigned char smraw[];
    __nv_bfloat16* base  = (__nv_bfloat16*)smraw;
    __nv_bfloat16* pAhi  = base;                 // 2 stages of G3_SA
    __nv_bfloat16* pAlo  = base + 2 * G3_SA;
    __nv_bfloat16* pBhi  = base + 4 * G3_SA;     // 2 stages of G3_SB
    __nv_bfloat16* pBlo  = base + 4 * G3_SA + 2 * G3_SB;
    float* sC = (float*)smraw;                   // epilogue reuse

    const int t    = threadIdx.x;
    const int warp = t >> 5;
    const int wm   = warp & 3;
    const int wn   = warp >> 2;
    const int n0   = blockIdx.x * 96;
    const int m0   = blockIdx.y * 128;

    wmma::fragment<wmma::accumulator, 16, 16, 16, float> acc[2][3];
    #pragma unroll
    for (int i = 0; i < 2; ++i)
        #pragma unroll
        for (int j = 0; j < 3; ++j)
            wmma::fill_fragment(acc[i][j], 0.f);

    // Prologue: stage 0 loads in flight
    g3_load_tile(t, m0, n0, 0, Ah, Al, Bh, Bl, pAhi, pAlo, pBhi, pBlo);
    asm volatile("cp.async.commit_group;\n" ::: "memory");

    for (int k0 = 0; k0 < G3_K; k0 += 32) {
        const int cur = (k0 >> 5) & 1;
        asm volatile("cp.async.wait_group 0;\n" ::: "memory");
        __syncthreads();

        if (k0 + 32 < G3_K) {
            const int nxt = cur ^ 1;
            g3_load_tile(t, m0, n0, k0 + 32, Ah, Al, Bh, Bl,
                         pAhi + nxt * G3_SA, pAlo + nxt * G3_SA,
                         pBhi + nxt * G3_SB, pBlo + nxt * G3_SB);
            asm volatile("cp.async.commit_group;\n" ::: "memory");
        }

        __nv_bfloat16* sAh = pAhi + cur * G3_SA;
        __nv_bfloat16* sAl = pAlo + cur * G3_SA;
        __nv_bfloat16* sBh = pBhi + cur * G3_SB;
        __nv_bfloat16* sBl = pBlo + cur * G3_SB;

        #pragma unroll
        for (int ks = 0; ks < 32; ks += 16) {
            wmma::fragment<wmma::matrix_a, 16, 16, 16, __nv_bfloat16, wmma::row_major> a_hi[2], a_lo[2];
            wmma::fragment<wmma::matrix_b, 16, 16, 16, __nv_bfloat16, wmma::row_major> b_hi[3], b_lo[3];
            #pragma unroll
            for (int i = 0; i < 2; ++i) {
                wmma::load_matrix_sync(a_hi[i], sAh + (wm * 32 + i * 16) * G3_AS + ks, G3_AS);
                wmma::load_matrix_sync(a_lo[i], sAl + (wm * 32 + i * 16) * G3_AS + ks, G3_AS);
            }
            #pragma unroll
            for (int j = 0; j < 3; ++j) {
                wmma::load_matrix_sync(b_hi[j], sBh + ks * G3_BS + wn * 48 + j * 16, G3_BS);
                wmma::load_matrix_sync(b_lo[j], sBl + ks * G3_BS + wn * 48 + j * 16, G3_BS);
            }
            #pragma unroll
            for (int i = 0; i < 2; ++i)
                #pragma unroll
                for (int j = 0; j < 3; ++j) {
                    wmma::mma_sync(acc[i][j], a_hi[i], b_hi[j], acc[i][j]);
                    wmma::mma_sync(acc[i][j], a_hi[i], b_lo[j], acc[i][j]);
                    wmma::mma_sync(acc[i][j], a_lo[i], b_hi[j], acc[i][j]);
                }
        }
    }

    // Epilogue
    __syncthreads();
    #pragma unroll
    for (int i = 0; i < 2; ++i)
        #pragma unroll
        for (int j = 0; j < 3; ++j)
            wmma::store_matrix_sync(sC + (wm * 32 + i * 16) * G3_SN + wn * 48 + j * 16,
                                    acc[i][j], G3_SN, wmma::mem_row_major);
    __syncthreads();
    for (int l = t; l < 128 * 96; l += 256) {
        int row = l / 96, col = l % 96;
        C[(size_t)(m0 + row) * G3_N + n0 + col] = sC[row * G3_SN + col] + bias[n0 + col];
    }
}

// ---------------------------------------------------------------------------
// QP solver — round-4 version verbatim (proven: 441 us). 256 thr / item.
// ---------------------------------------------------------------------------
__device__ __forceinline__ float sel16(const float* r, int kj) {
    float v = r[0];
    #pragma unroll
    for (int j = 1; j < 16; ++j) v = (j == kj) ? r[j] : v;
    return v;
}

#define SOLVER_SMEM_FLOATS (128 * 65 + 64 * 65)

__global__ __launch_bounds__(256, 2)
void solver_kernel(const float* __restrict__ out3, float* __restrict__ xs)
{
    extern __shared__ __align__(16) float smdyn[];
    float* sH = smdyn;              // 128*65
    float* sQ = sH + 128 * 65;      // 64*65

    __shared__ __align__(16) float spiv[2 * 64];
    __shared__ __align__(16) float sxbar[64];
    __shared__ __align__(16) float st[64];
    __shared__ __align__(16) float slam[128];
    __shared__ __align__(16) float sb[128];
    __shared__ __align__(16) float sq[64];
    __shared__ __align__(16) float sv[64];
    __shared__ __align__(16) float sw[128];
    __shared__ float spart[8];
    __shared__ float s_scal, s_tau;

    const int t    = threadIdx.x;
    const int lane = t & 31;
    const int warp = t >> 5;
    const int r    = t >> 1;
    const int h    = t & 1;
    const int c    = t >> 2;
    const int g    = t & 3;

    const float* row = out3 + (size_t)blockIdx.x * N_OUT;
    const unsigned FULL = 0xffffffffu;

    float rH[32];
    {
        const float4* base = (const float4*)(row + HOFF + r * 64 + 32 * h);
        #pragma unroll
        for (int k4 = 0; k4 < 8; ++k4) {
            float4 v = base[k4];
            rH[4*k4+0] = v.x; rH[4*k4+1] = v.y; rH[4*k4+2] = v.z; rH[4*k4+3] = v.w;
            sH[r * 65 + 32 * h + 4 * k4 + 0] = v.x;
            sH[r * 65 + 32 * h + 4 * k4 + 1] = v.y;
            sH[r * 65 + 32 * h + 4 * k4 + 2] = v.z;
            sH[r * 65 + 32 * h + 4 * k4 + 3] = v.w;
        }
    }
    if (t < 64)  sq[t] = row[N_P + t];
    if (t < 128) sb[t] = row[HOFF + N_HMAT + t];
    if (t < 64)  sv[t] = 0.125f;
    __syncthreads();

    for (int pit = 0; pit < 10; ++pit) {
        {
            const float4* x4 = (const float4*)(sv + 32 * h);
            float a0=0.f,a1=0.f,a2=0.f,a3=0.f;
            #pragma unroll
            for (int k4 = 0; k4 < 8; ++k4) {
                float4 xv = x4[k4];
                a0 = fmaf(rH[4*k4+0], xv.x, a0);
                a1 = fmaf(rH[4*k4+1], xv.y, a1);
                a2 = fmaf(rH[4*k4+2], xv.z, a2);
                a3 = fmaf(rH[4*k4+3], xv.w, a3);
            }
            float s = (a0 + a1) + (a2 + a3);
            s += __shfl_xor_sync(FULL, s, 1);
            if (h == 0) sw[r] = s;
        }
        __syncthreads();
        {
            float a0=0.f,a1=0.f,a2=0.f,a3=0.f;
            #pragma unroll
            for (int j0 = 0; j0 < 32; j0 += 4) {
                int jj0 = (j0 + 0 + 8 * g) & 31;
                int jj1 = (j0 + 1 + 8 * g) & 31;
                int jj2 = (j0 + 2 + 8 * g) & 31;
                int jj3 = (j0 + 3 + 8 * g) & 31;
                a0 = fmaf(sH[(32*g + jj0) * 65 + c], sw[32*g + jj0], a0);
                a1 = fmaf(sH[(32*g + jj1) * 65 + c], sw[32*g + jj1], a1);
                a2 = fmaf(sH[(32*g + jj2) * 65 + c], sw[32*g + jj2], a2);
                a3 = fmaf(sH[(32*g + jj3) * 65 + c], sw[32*g + jj3], a3);
            }
            float p = (a0 + a1) + (a2 + a3);
            p += __shfl_xor_sync(FULL, p, 1);
            p += __shfl_xor_sync(FULL, p, 2);
            float pp = (g == 0) ? p * p : 0.f;
            #pragma unroll
            for (int off = 16; off >= 1; off >>= 1)
                pp += __shfl_xor_sync(FULL, pp, off);
            if (lane == 0) spart[warp] = pp;
            __syncthreads();
            if (t == 0) {
                float sm = 0.f;
                #pragma unroll
                for (int i = 0; i < 8; ++i) sm += spart[i];
                s_scal = sqrtf(sm) + 1e-12f;
            }
            __syncthreads();
            if (g == 0) sv[c] = p / s_scal;
        }
        __syncthreads();
    }

    {
        const float4* x4 = (const float4*)(sv + 32 * h);
        float a0=0.f,a1=0.f,a2=0.f,a3=0.f;
        #pragma unroll
        for (int k4 = 0; k4 < 8; ++k4) {
            float4 xv = x4[k4];
            a0 = fmaf(rH[4*k4+0], xv.x, a0);
            a1 = fmaf(rH[4*k4+1], xv.y, a1);
            a2 = fmaf(rH[4*k4+2], xv.z, a2);
            a3 = fmaf(rH[4*k4+3], xv.w, a3);
        }
        float s = (a0 + a1) + (a2 + a3);
        s += __shfl_xor_sync(FULL, s, 1);
        float pp = (h == 0) ? s * s : 0.f;
        #pragma unroll
        for (int off = 16; off >= 1; off >>= 1)
            pp += __shfl_xor_sync(FULL, pp, off);
        if (lane == 0) spart[warp] = pp;
        __syncthreads();
        if (t == 0) {
            float sm = 0.f;
            #pragma unroll
            for (int i = 0; i < 8; ++i) sm += spart[i];
            s_tau = 0.9f / (sqrtf(sm) + 1e-6f);
        }
    }

    for (int idx = t; idx < 64 * 65; idx += 256) sQ[idx] = 0.f;
    __syncthreads();
    for (int idx = t; idx < N_P; idx += 256) {
        float p = row[idx];
        int rr = (int)((sqrtf(8.f * (float)idx + 1.f) - 1.f) * 0.5f);
        while ((rr * (rr + 1)) / 2 > idx) --rr;
        while (((rr + 1) * (rr + 2)) / 2 <= idx) ++rr;
        int cc = idx - (rr * (rr + 1)) / 2;
        float val;
        if (cc == rr) {
            float sp = fmaxf(p, 0.f) + log1pf(expf(-fabsf(p)));
            val = 0.1f + sp;
        } else {
            val = p;
        }
        sQ[rr * 65 + cc] = val;
    }
    __syncthreads();
    const float tau = s_tau;
    const float sig = tau;

    float rM[16];
    #pragma unroll
    for (int j = 0; j < 16; ++j) rM[j] = 0.f;
    for (int k = 0; k < 64; ++k) {
        float a = sQ[c * 65 + k];
        #pragma unroll
        for (int j = 0; j < 16; ++j)
            rM[j] = fmaf(a, sQ[(16 * g + j) * 65 + k], rM[j]);
    }
    #pragma unroll
    for (int j = 0; j < 16; ++j) {
        int col = 16 * g + j;
        rM[j] = tau * rM[j] + ((col == c) ? 1.f : 0.f);
    }
    __syncthreads();

    for (int k = 0; k < 64; ++k) {
        const int kc = k >> 4, kj = k & 15;
        float* buf = spiv + (k & 1) * 64;
        float praw = __shfl_sync(FULL, sel16(rM, kj), (lane & ~3) | kc);
        if (c == k) {
            float pinv = 1.f / praw;
            #pragma unroll
            for (int j = 0; j < 16; ++j) {
                bool isk = (g == kc) && (j == kj);
                rM[j] = isk ? pinv : rM[j] * pinv;
            }
            *(float4*)&buf[16*g +  0] = make_float4(rM[0],  rM[1],  rM[2],  rM[3]);
            *(float4*)&buf[16*g +  4] = make_float4(rM[4],  rM[5],  rM[6],  rM[7]);
            *(float4*)&buf[16*g +  8] = make_float4(rM[8],  rM[9],  rM[10], rM[11]);
            *(float4*)&buf[16*g + 12] = make_float4(rM[12], rM[13], rM[14], rM[15]);
        }
        __syncthreads();
        if (c != k) {
            const float f = praw;
            float4 p0 = *(const float4*)&buf[16*g +  0];
            float4 p1 = *(const float4*)&buf[16*g +  4];
            float4 p2 = *(const float4*)&buf[16*g +  8];
            float4 p3 = *(const float4*)&buf[16*g + 12];
            float pv[16] = {p0.x,p0.y,p0.z,p0.w, p1.x,p1.y,p1.z,p1.w,
                            p2.x,p2.y,p2.z,p2.w, p3.x,p3.y,p3.z,p3.w};
            #pragma unroll
            for (int j = 0; j < 16; ++j) {
                bool isk = (g == kc) && (j == kj);
                float upd = fmaf(-f, pv[j], rM[j]);
                rM[j] = isk ? (-f * pv[j]) : upd;
            }
        }
    }
    __syncthreads();

    if (t < 64)  { sxbar[t] = 0.f; st[t] = 0.f; }
    if (t < 128) slam[t] = 0.f;
    float xp = 0.f;
    __syncthreads();

    for (int it = 0; it < QP_ITER; ++it) {
        {
            const float4* x4 = (const float4*)(sxbar + 32 * h);
            float a0=0.f,a1=0.f,a2=0.f,a3=0.f;
            #pragma unroll
            for (int k4 = 0; k4 < 8; ++k4) {
                float4 xv = x4[k4];
                a0 = fmaf(rH[4*k4+0], xv.x, a0);
                a1 = fmaf(rH[4*k4+1], xv.y, a1);
                a2 = fmaf(rH[4*k4+2], xv.z, a2);
                a3 = fmaf(rH[4*k4+3], xv.w, a3);
            }
            float s = (a0 + a1) + (a2 + a3);
            s += __shfl_xor_sync(FULL, s, 1);
            if (h == 0) slam[r] = fmaxf(0.f, slam[r] - sig * (s + sb[r]));
        }
        __syncthreads();
        {
            float a0=0.f,a1=0.f,a2=0.f,a3=0.f;
            #pragma unroll
            for (int j0 = 0; j0 < 32; j0 += 4) {
                int jj0 = (j0 + 0 + 8 * g) & 31;
                int jj1 = (j0 + 1 + 8 * g) & 31;
                int jj2 = (j0 + 2 + 8 * g) & 31;
                int jj3 = (j0 + 3 + 8 * g) & 31;
                a0 = fmaf(sH[(32*g + jj0) * 65 + c], slam[32*g + jj0], a0);
                a1 = fmaf(sH[(32*g + jj1) * 65 + c], slam[32*g + jj1], a1);
                a2 = fmaf(sH[(32*g + jj2) * 65 + c], slam[32*g + jj2], a2);
                a3 = fmaf(sH[(32*g + jj3) * 65 + c], slam[32*g + jj3], a3);
            }
            float p = (a0 + a1) + (a2 + a3);
            p += __shfl_xor_sync(FULL, p, 1);
            p += __shfl_xor_sync(FULL, p, 2);
            if (g == 0) st[c] = xp + tau * (p - sq[c]);
        }
        __syncthreads();
        {
            const float4* t4 = (const float4*)(st + 16 * g);
            float4 t0 = t4[0], t1 = t4[1], t2 = t4[2], t3 = t4[3];
            float a0=0.f,a1=0.f,a2=0.f,a3=0.f;
            a0 = fmaf(rM[0],  t0.x, a0); a1 = fmaf(rM[1],  t0.y, a1);
            a2 = fmaf(rM[2],  t0.z, a2); a3 = fmaf(rM[3],  t0.w, a3);
            a0 = fmaf(rM[4],  t1.x, a0); a1 = fmaf(rM[5],  t1.y, a1);
            a2 = fmaf(rM[6],  t1.z, a2); a3 = fmaf(rM[7],  t1.w, a3);
            a0 = fmaf(rM[8],  t2.x, a0); a1 = fmaf(rM[9],  t2.y, a1);
            a2 = fmaf(rM[10], t2.z, a2); a3 = fmaf(rM[11], t2.w, a3);
            a0 = fmaf(rM[12], t3.x, a0); a1 = fmaf(rM[13], t3.y, a1);
            a2 = fmaf(rM[14], t3.z, a2); a3 = fmaf(rM[15], t3.w, a3);
            float p = (a0 + a1) + (a2 + a3);
            p += __shfl_xor_sync(FULL, p, 1);
            p += __shfl_xor_sync(FULL, p, 2);
            if (g == 0) {
                sxbar[c] = 2.f * p - xp;
                xp = p;
            }
        }
        __syncthreads();
    }

    if (g == 0) xs[(size_t)blockIdx.x * N_QP + c] = xp;
}

// ---------------------------------------------------------------------------
// Launch
// ---------------------------------------------------------------------------
extern "C" void kernel_launch(void* const* d_in, const int* in_sizes, int n_in,
                              void* d_out, int out_size)
{
    const float* x  = (const float*)d_in[0];
    const float* W1 = (const float*)d_in[1];
    const float* b1 = (const float*)d_in[2];
    const float* W2 = (const float*)d_in[3];
    const float* b2 = (const float*)d_in[4];
    const float* W3 = (const float*)d_in[5];
    const float* b3 = (const float*)d_in[6];
    float* out = (float*)d_out;

    float *p_h1, *p_h2, *p_out3;
    __nv_bfloat16 *p_ahi, *p_alo, *p_bhi, *p_blo;
    cudaGetSymbolAddress((void**)&p_h1, g_h1);
    cudaGetSymbolAddress((void**)&p_h2, g_h2);
    cudaGetSymbolAddress((void**)&p_out3, g_out3);
    cudaGetSymbolAddress((void**)&p_ahi, g_a_hi);
    cudaGetSymbolAddress((void**)&p_alo, g_a_lo);
    cudaGetSymbolAddress((void**)&p_bhi, g_b_hi);
    cudaGetSymbolAddress((void**)&p_blo, g_b_lo);

    {
        dim3 grid(HIDDEN / 64, BATCH / 64);
        sgemm_bias<true><<<grid, 256>>>(x, W1, b1, p_h1, BATCH, HIDDEN, INPUT_SIZE);
    }
    {
        dim3 grid(HIDDEN / 64, BATCH / 64);
        sgemm_bias<true><<<grid, 256>>>(p_h1, W2, b2, p_h2, BATCH, HIDDEN, HIDDEN);
    }
    {
        int n4 = (HIDDEN * N_OUT) / 4;
        split_kernel<<<(n4 + 255) / 256, 256>>>(W3, p_bhi, p_blo, n4);
    }
    {
        int n4 = (BATCH * HIDDEN) / 4;
        split_kernel<<<(n4 + 255) / 256, 256>>>(p_h2, p_ahi, p_alo, n4);
    }
    {
        cudaFuncSetAttribute(gemm3_bf16,
                             cudaFuncAttributeMaxDynamicSharedMemorySize,
                             G3_SMEM_BYTES);
        dim3 grid(G3_N / 96, BATCH / 128);   // 109 x 8
        gemm3_bf16<<<grid, 256, G3_SMEM_BYTES>>>(p_ahi, p_alo, p_bhi, p_blo, b3, p_out3);
    }
    {
        const size_t smem_bytes = (size_t)SOLVER_SMEM_FLOATS * sizeof(float);
        cudaFuncSetAttribute(solver_kernel,
                             cudaFuncAttributeMaxDynamicSharedMemorySize,
                             (int)smem_bytes);
        solver_kernel<<<BATCH, 256, smem_bytes>>>(p_out3, out);
    }
}